// round 2
// baseline (speedup 1.0000x reference)
#include <cuda_runtime.h>
#include <cuda_bf16.h>
#include <cstdint>

#define BATCH 32
#define CIN   256
#define HH    28
#define WW    28
#define NP    1024
#define OHH   26
#define OWW   26
#define NPATCH (OHH*OWW)       /* 676 */
#define SP    768              /* padded patch count */
#define KTOT  2304
#define IMG   (CIN*HH*WW)
#define PLANE (HH*WW)
#define KC    32
#define NCHUNK (KTOT/KC)       /* 72 */

__device__ __nv_bfloat16 g_xcol[(size_t)BATCH*KTOT*SP];  // im2col, k=(kh*3+kw)*256+c
__device__ __nv_bfloat16 g_pbf[(size_t)NP*KTOT];         // protos, same k order
__device__ float g_pssq[NP];
__device__ float g_S[BATCH*PLANE];
__device__ float g_xssq[BATCH*NPATCH];

// ---------- prep ----------
__global__ void k_im2col(const float* __restrict__ x) {
    int idx = blockIdx.x * blockDim.x + threadIdx.x;
    if (idx >= BATCH*KTOT*SP) return;
    int s = idx % SP;
    int t = idx / SP;
    int k = t % KTOT;
    int b = t / KTOT;
    float v = 0.f;
    if (s < NPATCH) {
        int r = k >> 8, c = k & 255;
        int kh = r / 3, kw = r - kh*3;
        int oh = s / OWW, ow = s - oh*OWW;
        v = x[((size_t)(b*CIN + c)*HH + oh + kh)*WW + ow + kw];
    }
    g_xcol[idx] = __float2bfloat16(v);
}

__global__ void k_proto(const float* __restrict__ proto) {
    int p = blockIdx.x, tid = threadIdx.x;
    const float* row = proto + (size_t)p*KTOT;
    float s = 0.f;
    for (int idx = tid; idx < KTOT; idx += 256) {
        float v = row[idx];
        int c = idx / 9, r = idx - c*9;
        g_pbf[(size_t)p*KTOT + r*CIN + c] = __float2bfloat16(v);
        s += v*v;
    }
    #pragma unroll
    for (int o = 16; o > 0; o >>= 1) s += __shfl_down_sync(0xffffffffu, s, o);
    __shared__ float red[8];
    if ((tid & 31) == 0) red[tid >> 5] = s;
    __syncthreads();
    if (tid == 0) {
        float t = 0.f;
        #pragma unroll
        for (int i = 0; i < 8; i++) t += red[i];
        g_pssq[p] = t;
    }
}

__global__ void k_chansq(const float* __restrict__ x) {
    int i = blockIdx.x * blockDim.x + threadIdx.x;
    if (i >= BATCH*PLANE) return;
    int b = i / PLANE, hw = i - b*PLANE;
    const float* px = x + (size_t)b*IMG + hw;
    float s = 0.f;
    #pragma unroll 8
    for (int c = 0; c < CIN; c++) { float v = px[(size_t)c*PLANE]; s += v*v; }
    g_S[i] = s;
}

__global__ void k_boxsum() {
    int j = blockIdx.x * blockDim.x + threadIdx.x;
    if (j >= BATCH*NPATCH) return;
    int b = j / NPATCH, s = j - b*NPATCH;
    int oh = s / OWW, ow = s - oh*OWW;
    const float* pS = g_S + (size_t)b*PLANE + oh*WW + ow;
    float acc = 0.f;
    #pragma unroll
    for (int kh = 0; kh < 3; kh++)
        #pragma unroll
        for (int kw = 0; kw < 3; kw++) acc += pS[kh*WW + kw];
    g_xssq[j] = acc;
}

// ---------- GEMM ----------
#define PADA 40
#define PADB 136

__device__ __forceinline__ uint32_t cvta_s(const void* p) {
    return (uint32_t)__cvta_generic_to_shared(p);
}
__device__ __forceinline__ void ldsm4(uint32_t* r, uint32_t a) {
    asm volatile("ldmatrix.sync.aligned.m8n8.x4.shared.b16 {%0,%1,%2,%3}, [%4];"
                 : "=r"(r[0]), "=r"(r[1]), "=r"(r[2]), "=r"(r[3]) : "r"(a));
}
__device__ __forceinline__ void ldsm4t(uint32_t* r, uint32_t a) {
    asm volatile("ldmatrix.sync.aligned.m8n8.x4.trans.shared.b16 {%0,%1,%2,%3}, [%4];"
                 : "=r"(r[0]), "=r"(r[1]), "=r"(r[2]), "=r"(r[3]) : "r"(a));
}
__device__ __forceinline__ void mma(float* d, const uint32_t* a, uint32_t b0, uint32_t b1) {
    asm volatile("mma.sync.aligned.m16n8k16.row.col.f32.bf16.bf16.f32 "
                 "{%0,%1,%2,%3},{%4,%5,%6,%7},{%8,%9},{%0,%1,%2,%3};"
                 : "+f"(d[0]), "+f"(d[1]), "+f"(d[2]), "+f"(d[3])
                 : "r"(a[0]), "r"(a[1]), "r"(a[2]), "r"(a[3]), "r"(b0), "r"(b1));
}

__global__ void __launch_bounds__(256, 2) k_gemm(float* __restrict__ out) {
    __shared__ __align__(16) __nv_bfloat16 sA[2][128][PADA];
    __shared__ __align__(16) __nv_bfloat16 sB[2][KC][PADB];
    __shared__ float psq_sh[128];
    __shared__ float xsq_sh[128];

    const int tid    = threadIdx.x;
    const int b      = blockIdx.z;
    const int sblock = blockIdx.y * 128;
    const int pblock = blockIdx.x * 128;

    {
        int sl = tid & 127;
        if (tid < 128) {
            int sg = sblock + sl;
            xsq_sh[sl] = (sg < NPATCH) ? g_xssq[b*NPATCH + sg] : 0.f;
        } else {
            psq_sh[sl] = g_pssq[pblock + sl];
        }
    }

    const uint32_t sA0 = cvta_s(&sA[0][0][0]);
    const uint32_t sB0 = cvta_s(&sB[0][0][0]);
    const __nv_bfloat16* Xb = g_xcol + (size_t)b*KTOT*SP;
    const __nv_bfloat16* Pb = g_pbf + (size_t)pblock*KTOT;

    // B: 512 16B vecs -> v, v+256 ; A: 512 16B vecs -> v, v+256
    auto prefetch = [&](int kc, int st) {
        #pragma unroll
        for (int h = 0; h < 2; h++) {
            int v = tid + h*256;
            int t = v >> 4, c8 = (v & 15) * 8;
            const __nv_bfloat16* src = Xb + (size_t)(kc*KC + t)*SP + sblock + c8;
            uint32_t dst = sB0 + (uint32_t)(((st*KC + t)*PADB + c8) * 2);
            asm volatile("cp.async.cg.shared.global [%0], [%1], 16;" :: "r"(dst), "l"(src));
        }
        #pragma unroll
        for (int h = 0; h < 2; h++) {
            int v = tid + h*256;
            int row = v >> 2, c8 = (v & 3) * 8;
            const __nv_bfloat16* src = Pb + (size_t)row*KTOT + kc*KC + c8;
            uint32_t dst = sA0 + (uint32_t)(((st*128 + row)*PADA + c8) * 2);
            asm volatile("cp.async.cg.shared.global [%0], [%1], 16;" :: "r"(dst), "l"(src));
        }
        asm volatile("cp.async.commit_group;");
    };

    prefetch(0, 0);
    prefetch(1, 1);

    const int lane = tid & 31;
    const int warp = tid >> 5;
    const int wm = warp >> 1;   // 0..3 -> 32-row proto strip
    const int wn = warp & 1;    // 0..1 -> 64-col patch strip
    const int lr = lane & 15;
    const int lc = (lane >> 4) * 8;

    float acc[2][8][4];
    #pragma unroll
    for (int i = 0; i < 2; i++)
        #pragma unroll
        for (int j = 0; j < 8; j++)
            #pragma unroll
            for (int q = 0; q < 4; q++) acc[i][j][q] = 0.f;

    for (int kc = 0; kc < NCHUNK; kc++) {
        if (kc < NCHUNK - 1) asm volatile("cp.async.wait_group 1;" ::: "memory");
        else                 asm volatile("cp.async.wait_group 0;" ::: "memory");
        __syncthreads();
        int st = kc & 1;
        #pragma unroll
        for (int ks = 0; ks < 2; ks++) {
            uint32_t a[2][4], bq[4][4];
            #pragma unroll
            for (int im = 0; im < 2; im++) {
                uint32_t addr = sA0 + (uint32_t)(((st*128 + wm*32 + im*16 + lr)*PADA + ks*16 + lc) * 2);
                ldsm4(a[im], addr);
            }
            #pragma unroll
            for (int q = 0; q < 4; q++) {
                uint32_t addr = sB0 + (uint32_t)(((st*KC + ks*16 + lr)*PADB + wn*64 + q*16 + lc) * 2);
                ldsm4t(bq[q], addr);
            }
            #pragma unroll
            for (int im = 0; im < 2; im++)
                #pragma unroll
                for (int nt = 0; nt < 8; nt++)
                    mma(acc[im][nt], a[im], bq[nt >> 1][(nt & 1)*2], bq[nt >> 1][(nt & 1)*2 + 1]);
        }
        __syncthreads();
        if (kc + 2 < NCHUNK) prefetch(kc + 2, st);
    }

    // epilogue: d2 = xs - 2*acc + ps ; out = sqrt(max(d2, 1e-14))
    const int col = (lane & 3) * 2;
    const int row = lane >> 2;
    #pragma unroll
    for (int im = 0; im < 2; im++) {
        #pragma unroll
        for (int nt = 0; nt < 8; nt++) {
            int n = wn*64 + nt*8 + col;
            int sg = sblock + n;
            if (sg >= NPATCH) continue;
            float xs0 = xsq_sh[n], xs1 = xsq_sh[n + 1];
            #pragma unroll
            for (int i = 0; i < 2; i++) {
                int ml = wm*32 + im*16 + row + i*8;
                float ps = psq_sh[ml];
                float v0 = fmaxf(xs0 - 2.f*acc[im][nt][2*i]     + ps, 1e-14f);
                float v1 = fmaxf(xs1 - 2.f*acc[im][nt][2*i + 1] + ps, 1e-14f);
                float2 o = make_float2(sqrtf(v0), sqrtf(v1));
                *reinterpret_cast<float2*>(out + ((size_t)(b*NP + pblock + ml)*NPATCH + sg)) = o;
            }
        }
    }
}

extern "C" void kernel_launch(void* const* d_in, const int* in_sizes, int n_in,
                              void* d_out, int out_size) {
    const float* x     = (const float*)d_in[0];
    const float* proto = (const float*)d_in[1];
    if (in_sizes[0] == NP*KTOT) { const float* t = x; x = proto; proto = t; }
    float* out = (float*)d_out;

    int toti = BATCH*KTOT*SP;
    k_im2col<<<(toti + 255) / 256, 256>>>(x);
    k_proto<<<NP, 256>>>(proto);
    k_chansq<<<(BATCH*PLANE + 255) / 256, 256>>>(x);
    k_boxsum<<<(BATCH*NPATCH + 255) / 256, 256>>>();

    dim3 grid(NP/128, (NPATCH + 127) / 128, BATCH);
    k_gemm<<<grid, 256>>>(out);
}